// round 4
// baseline (speedup 1.0000x reference)
#include <cuda_runtime.h>

typedef unsigned long long u64;

#define B_SZ   8192
#define NPROD  50
#define DXF    32
#define DZF    20
#define NROWS  (B_SZ * NPROD)       // 409600

// ---------------- scratch (device globals, no allocation) ----------------
__device__ float g_Zj[3 * B_SZ * 16];            // [KZ][B][16]
__device__ float g_Xi[3 * NROWS * 16];           // [KX][B*n][16]
__device__ float g_scores[9 * NROWS];            // [pair][B][n]

// ---------------- packed f32x2 helpers ----------------
__device__ __forceinline__ u64 pk2(float lo, float hi) {
    u64 r; asm("mov.b64 %0, {%1, %2};" : "=l"(r) : "f"(lo), "f"(hi)); return r;
}
__device__ __forceinline__ void upk2(u64 v, float& lo, float& hi) {
    asm("mov.b64 {%0, %1}, %2;" : "=f"(lo), "=f"(hi) : "l"(v));
}
__device__ __forceinline__ void f2fma(u64& d, u64 a, u64 b) {
    asm("fma.rn.f32x2 %0, %1, %2, %0;" : "+l"(d) : "l"(a), "l"(b));
}
__device__ __forceinline__ float eluf(float x) { return x > 0.f ? x : expm1f(x); }

// Dense layer with register-resident input/output, weights in shared.
// wsh layout: [IN][OUT] row-major, OUT multiple of 4.
template<int IN, int OUT, bool ELU>
__device__ __forceinline__ void dense_reg(const float (&in)[IN], const float* wsh, float (&out)[OUT]) {
    u64 acc[OUT / 2];
#pragma unroll
    for (int jj = 0; jj < OUT / 2; jj++) acc[jj] = 0ull;
#pragma unroll
    for (int k = 0; k < IN; k++) {
        u64 xk = pk2(in[k], in[k]);
        const ulonglong2* w = (const ulonglong2*)(wsh + k * OUT);
#pragma unroll
        for (int q = 0; q < OUT / 4; q++) {
            ulonglong2 ww = w[q];
            f2fma(acc[2 * q],     xk, ww.x);
            f2fma(acc[2 * q + 1], xk, ww.y);
        }
    }
#pragma unroll
    for (int jj = 0; jj < OUT / 2; jj++) {
        float lo, hi; upk2(acc[jj], lo, hi);
        out[2 * jj]     = ELU ? eluf(lo) : lo;
        out[2 * jj + 1] = ELU ? eluf(hi) : hi;
    }
}

// Dense 128-wide layer, input from per-thread shared slab, acc packed in regs.
template<int IN>
__device__ __forceinline__ void dense128_slab(const float* my, const float* wsh, u64 (&acc)[64]) {
#pragma unroll
    for (int jj = 0; jj < 64; jj++) acc[jj] = 0ull;
#pragma unroll 2
    for (int k = 0; k < IN; k++) {
        float ukf = my[k];
        u64 uk = pk2(ukf, ukf);
        const ulonglong2* w = (const ulonglong2*)(wsh + k * 128);
#pragma unroll
        for (int q = 0; q < 32; q++) {
            ulonglong2 ww = w[q];
            f2fma(acc[2 * q],     uk, ww.x);
            f2fma(acc[2 * q + 1], uk, ww.y);
        }
    }
}

// ============================================================
// Kernel 1: Z-branch.  Zj[j][b][:] = MLP_j(Z[b])
// grid 192 blocks x 128 threads: blockIdx >> 6 = j, rest picks 128 b's.
// ============================================================
__global__ void __launch_bounds__(128) z_kernel(const float* __restrict__ Zin,
                                                const float* __restrict__ Wz0,
                                                const float* __restrict__ Wz,
                                                const float* __restrict__ Wlz) {
    __shared__ __align__(16) float w0[20 * 64];
    __shared__ __align__(16) float w1[64 * 64];
    __shared__ __align__(16) float w2[64 * 64];
    __shared__ __align__(16) float wl[64 * 16];
    const int j   = blockIdx.x >> 6;
    const int tid = threadIdx.x;
    const int b   = ((blockIdx.x & 63) << 7) + tid;

    {
        const float4* p0 = (const float4*)(Wz0 + j * 1280);
        const float4* p1 = (const float4*)(Wz  + j * 8192);
        const float4* p2 = (const float4*)(Wz  + j * 8192 + 4096);
        const float4* pl = (const float4*)(Wlz + j * 1024);
        for (int t = tid; t < 320;  t += 128) ((float4*)w0)[t] = p0[t];
        for (int t = tid; t < 1024; t += 128) ((float4*)w1)[t] = p1[t];
        for (int t = tid; t < 1024; t += 128) ((float4*)w2)[t] = p2[t];
        for (int t = tid; t < 256;  t += 128) ((float4*)wl)[t] = pl[t];
    }
    __syncthreads();

    float zv[20];
    const float4* zr = (const float4*)(Zin + (size_t)b * DZF);
#pragma unroll
    for (int t = 0; t < 5; t++) {
        float4 v = zr[t];
        zv[4 * t] = v.x; zv[4 * t + 1] = v.y; zv[4 * t + 2] = v.z; zv[4 * t + 3] = v.w;
    }

    float h1[64], h2[64], o[16];
    dense_reg<20, 64, true >(zv, w0, h1);
    dense_reg<64, 64, true >(h1, w1, h2);
    dense_reg<64, 64, true >(h2, w2, h1);
    dense_reg<64, 16, false>(h1, wl, o);

    float4* dst = (float4*)(g_Zj + (size_t)(j * B_SZ + b) * 16);
#pragma unroll
    for (int t = 0; t < 4; t++)
        dst[t] = make_float4(o[4 * t], o[4 * t + 1], o[4 * t + 2], o[4 * t + 3]);
}

// ============================================================
// Kernel 2: X-branch.  Xi[i][b*n+p][:] = MLP_i(X[b,p])
// NOTE: last layer uses Wlx[DX-1] for EVERY i (faithful to reference bug).
// grid (1600, 3) x 256 threads.
// ============================================================
__global__ void __launch_bounds__(256) x_kernel(const float* __restrict__ Xin,
                                                const float* __restrict__ Wx0,
                                                const float* __restrict__ Wx,
                                                const float* __restrict__ Wlx) {
    __shared__ __align__(16) float w0[32 * 64];
    __shared__ __align__(16) float w1[64 * 64];
    __shared__ __align__(16) float w2[64 * 64];
    __shared__ __align__(16) float wl[64 * 16];
    const int i   = blockIdx.y;
    const int tid = threadIdx.x;

    {
        const float4* p0 = (const float4*)(Wx0 + i * 2048);
        const float4* p1 = (const float4*)(Wx  + i * 8192);
        const float4* p2 = (const float4*)(Wx  + i * 8192 + 4096);
        const float4* pl = (const float4*)(Wlx + 2 * 1024);   // Wlx[DX-1] always
        for (int t = tid; t < 512;  t += 256) ((float4*)w0)[t] = p0[t];
        for (int t = tid; t < 1024; t += 256) ((float4*)w1)[t] = p1[t];
        for (int t = tid; t < 1024; t += 256) ((float4*)w2)[t] = p2[t];
        for (int t = tid; t < 256;  t += 256) ((float4*)wl)[t] = pl[t];
    }
    __syncthreads();

    const int r = blockIdx.x * 256 + tid;  // row in [0, NROWS)
    float xv[32];
    const float4* xr = (const float4*)(Xin + (size_t)r * DXF);
#pragma unroll
    for (int t = 0; t < 8; t++) {
        float4 v = xr[t];
        xv[4 * t] = v.x; xv[4 * t + 1] = v.y; xv[4 * t + 2] = v.z; xv[4 * t + 3] = v.w;
    }

    float h1[64], h2[64], o[16];
    dense_reg<32, 64, true >(xv, w0, h1);
    dense_reg<64, 64, true >(h1, w1, h2);
    dense_reg<64, 64, true >(h2, w2, h1);
    dense_reg<64, 16, false>(h1, wl, o);

    float4* dst = (float4*)(g_Xi + (size_t)(i * NROWS + r) * 16);
#pragma unroll
    for (int t = 0; t < 4; t++)
        dst[t] = make_float4(o[4 * t], o[4 * t + 1], o[4 * t + 2], o[4 * t + 3]);
}

// ============================================================
// Kernel 3: U-branch scores over all 9 (i,j) pairs.
// Row r = (pair*B + b)*n + p.  Per-thread activation slab in shared
// (width 129 -> bank-conflict-free), weights staged layer-by-layer in
// a 64KB shared buffer, 128 packed fp32 accumulators in registers.
// grid 14400 x 256, dynamic smem ~194KB.
// ============================================================
__global__ void __launch_bounds__(256) u_kernel(const float* __restrict__ X,
                                                const float* __restrict__ Z,
                                                const float* __restrict__ Wu0,
                                                const float* __restrict__ Wu,
                                                const float* __restrict__ Wlast) {
    extern __shared__ float smem[];
    float* slab    = smem;                   // 256 * 129 floats
    float* wbuf    = smem + 256 * 129;       // 16384 floats
    float* wlastsh = wbuf + 16384;           // 128 floats

    const int tid  = threadIdx.x;
    const int r    = blockIdx.x * 256 + tid;         // [0, 9*409600)
    const int pair = r / NROWS;
    const int rem  = r - pair * NROWS;
    const int b    = rem / NPROD;
    const int p    = rem - b * NPROD;
    const int i    = pair / 3;
    const int j    = pair - 3 * i;
    float* my = slab + tid * 129;

    // ---- gather input u_in[84] = [X(32) | Xi(16) | Zj(16) | Z(20)] ----
    {
        const float4* xr = (const float4*)(X + (size_t)(b * NPROD + p) * DXF);
#pragma unroll
        for (int t = 0; t < 8; t++) {
            float4 v = xr[t];
            my[4 * t] = v.x; my[4 * t + 1] = v.y; my[4 * t + 2] = v.z; my[4 * t + 3] = v.w;
        }
        const float4* xir = (const float4*)(g_Xi + (size_t)(i * NROWS + b * NPROD + p) * 16);
#pragma unroll
        for (int t = 0; t < 4; t++) {
            float4 v = xir[t];
            my[32 + 4 * t] = v.x; my[33 + 4 * t] = v.y; my[34 + 4 * t] = v.z; my[35 + 4 * t] = v.w;
        }
        const float4* zjr = (const float4*)(g_Zj + (size_t)(j * B_SZ + b) * 16);
#pragma unroll
        for (int t = 0; t < 4; t++) {
            float4 v = zjr[t];
            my[48 + 4 * t] = v.x; my[49 + 4 * t] = v.y; my[50 + 4 * t] = v.z; my[51 + 4 * t] = v.w;
        }
        const float4* zr = (const float4*)(Z + (size_t)b * DZF);
#pragma unroll
        for (int t = 0; t < 5; t++) {
            float4 v = zr[t];
            my[64 + 4 * t] = v.x; my[65 + 4 * t] = v.y; my[66 + 4 * t] = v.z; my[67 + 4 * t] = v.w;
        }
    }

    // ---- layer 1: 84 -> 128 (Wu0) ----
    for (int t = tid; t < 2688; t += 256) ((float4*)wbuf)[t] = ((const float4*)Wu0)[t];
    if (tid < 32) ((float4*)wlastsh)[tid] = ((const float4*)Wlast)[tid];
    __syncthreads();

    u64 acc[64];
    dense128_slab<84>(my, wbuf, acc);
#pragma unroll
    for (int jj = 0; jj < 64; jj++) {
        float lo, hi; upk2(acc[jj], lo, hi);
        my[2 * jj] = eluf(lo); my[2 * jj + 1] = eluf(hi);
    }

    // ---- layer 2: 128 -> 128 (Wu[0]) ----
    __syncthreads();
    for (int t = tid; t < 4096; t += 256) ((float4*)wbuf)[t] = ((const float4*)Wu)[t];
    __syncthreads();
    dense128_slab<128>(my, wbuf, acc);
#pragma unroll
    for (int jj = 0; jj < 64; jj++) {
        float lo, hi; upk2(acc[jj], lo, hi);
        my[2 * jj] = eluf(lo); my[2 * jj + 1] = eluf(hi);
    }

    // ---- layer 3: 128 -> 128 (Wu[1]) + dot with Wlast ----
    __syncthreads();
    for (int t = tid; t < 4096; t += 256) ((float4*)wbuf)[t] = ((const float4*)(Wu + 16384))[t];
    __syncthreads();
    dense128_slab<128>(my, wbuf, acc);

    float s = 0.f;
#pragma unroll
    for (int jj = 0; jj < 64; jj++) {
        float lo, hi; upk2(acc[jj], lo, hi);
        s += eluf(lo) * wlastsh[2 * jj] + eluf(hi) * wlastsh[2 * jj + 1];
    }
    g_scores[r] = s;
}

// ============================================================
// Kernel 4: softmax over n per (pair, b), accumulate & average.
// out[b,p] = (1/9) * sum_pairs (TOL + softmax(score))/(1 + TOL*n)
// ============================================================
__global__ void __launch_bounds__(64) smax_kernel(float* __restrict__ out) {
    __shared__ float red[64];
    const int b   = blockIdx.x;
    const int tid = threadIdx.x;
    const bool act = tid < NPROD;
    float accv = 0.f;

    for (int pair = 0; pair < 9; pair++) {
        float s = act ? g_scores[(size_t)(pair * B_SZ + b) * NPROD + tid] : -1e30f;
        red[tid] = s;
        __syncthreads();
#pragma unroll
        for (int st = 32; st > 0; st >>= 1) {
            if (tid < st) red[tid] = fmaxf(red[tid], red[tid + st]);
            __syncthreads();
        }
        float mx = red[0];
        __syncthreads();
        float e = act ? expf(s - mx) : 0.f;
        red[tid] = e;
        __syncthreads();
#pragma unroll
        for (int st = 32; st > 0; st >>= 1) {
            if (tid < st) red[tid] += red[tid + st];
            __syncthreads();
        }
        float sum = red[0];
        __syncthreads();
        accv += 1e-6f + e / sum;
    }
    if (act)
        out[(size_t)b * NPROD + tid] = accv * (1.f / (1.f + 1e-6f * (float)NPROD)) / 9.f;
}

// ============================================================
extern "C" void kernel_launch(void* const* d_in, const int* in_sizes, int n_in,
                              void* d_out, int out_size) {
    const float* X     = (const float*)d_in[0];
    const float* Z     = (const float*)d_in[1];
    const float* Wx0   = (const float*)d_in[2];
    const float* Wx    = (const float*)d_in[3];
    const float* Wlx   = (const float*)d_in[4];
    const float* Wz0   = (const float*)d_in[5];
    const float* Wz    = (const float*)d_in[6];
    const float* Wlz   = (const float*)d_in[7];
    const float* Wu0   = (const float*)d_in[8];
    const float* Wu    = (const float*)d_in[9];
    const float* Wlast = (const float*)d_in[10];
    float* out = (float*)d_out;

    const size_t smemU = (size_t)(256 * 129 + 16384 + 128) * sizeof(float); // 198144 B
    cudaFuncSetAttribute(u_kernel, cudaFuncAttributeMaxDynamicSharedMemorySize, (int)smemU);

    z_kernel<<<192, 128>>>(Z, Wz0, Wz, Wlz);
    x_kernel<<<dim3(1600, 3), 256>>>(X, Wx0, Wx, Wlx);
    u_kernel<<<14400, 256, smemU>>>(X, Z, Wu0, Wu, Wlast);
    smax_kernel<<<8192, 64>>>(out);
}

// round 5
// speedup vs baseline: 1.0492x; 1.0492x over previous
#include <cuda_runtime.h>

typedef unsigned long long u64;

#define B_SZ   8192
#define NPROD  50
#define DXF    32
#define DZF    20
#define NROWS  (B_SZ * NPROD)       // 409600

// ---------------- scratch (device globals, no allocation) ----------------
__device__ float g_Zj[3 * B_SZ * 16];                    // [KZ][B][16]
__device__ float g_D[3 * B_SZ * 128];                    // [KZ][B][128]  (Zj,Z part of layer1)
__device__ float g_E[(size_t)3 * 128 * NROWS];           // [KX][128][NROWS] column-major
__device__ float g_scores[9 * NROWS];                    // [pair][B][n]

// ---------------- packed f32x2 helpers ----------------
__device__ __forceinline__ u64 pk2(float lo, float hi) {
    u64 r; asm("mov.b64 %0, {%1, %2};" : "=l"(r) : "f"(lo), "f"(hi)); return r;
}
__device__ __forceinline__ void upk2(u64 v, float& lo, float& hi) {
    asm("mov.b64 {%0, %1}, %2;" : "=f"(lo), "=f"(hi) : "l"(v));
}
__device__ __forceinline__ void f2fma(u64& d, u64 a, u64 b) {
    asm("fma.rn.f32x2 %0, %1, %2, %0;" : "+l"(d) : "l"(a), "l"(b));
}
__device__ __forceinline__ float eluf(float x) { return x > 0.f ? x : expm1f(x); }

// Dense layer, register input/output, weights in shared. [IN][OUT] row-major.
template<int IN, int OUT, bool ELU>
__device__ __forceinline__ void dense_reg(const float (&in)[IN], const float* wsh, float (&out)[OUT]) {
    u64 acc[OUT / 2];
#pragma unroll
    for (int jj = 0; jj < OUT / 2; jj++) acc[jj] = 0ull;
#pragma unroll
    for (int k = 0; k < IN; k++) {
        u64 xk = pk2(in[k], in[k]);
        const ulonglong2* w = (const ulonglong2*)(wsh + k * OUT);
#pragma unroll
        for (int q = 0; q < OUT / 4; q++) {
            ulonglong2 ww = w[q];
            f2fma(acc[2 * q],     xk, ww.x);
            f2fma(acc[2 * q + 1], xk, ww.y);
        }
    }
#pragma unroll
    for (int jj = 0; jj < OUT / 2; jj++) {
        float lo, hi; upk2(acc[jj], lo, hi);
        out[2 * jj]     = ELU ? eluf(lo) : lo;
        out[2 * jj + 1] = ELU ? eluf(hi) : hi;
    }
}

// Half-width (64-out) accumulation pass, register input, weight row stride 128.
template<int IN>
__device__ __forceinline__ void dense_half_reg(const float (&in)[IN], const float* wcol, u64 (&acc)[32]) {
#pragma unroll
    for (int q = 0; q < 32; q++) acc[q] = 0ull;
#pragma unroll
    for (int k = 0; k < IN; k++) {
        u64 uk = pk2(in[k], in[k]);
        const ulonglong2* w = (const ulonglong2*)(wcol + k * 128);
#pragma unroll
        for (int q = 0; q < 16; q++) {
            ulonglong2 ww = w[q];
            f2fma(acc[2 * q],     uk, ww.x);
            f2fma(acc[2 * q + 1], uk, ww.y);
        }
    }
}

// Half-width pass, input from per-thread shared slab (width-129 rows).
template<int IN>
__device__ __forceinline__ void dense_half_slab(const float* my, const float* wcol, u64 (&acc)[32]) {
#pragma unroll
    for (int q = 0; q < 32; q++) acc[q] = 0ull;
#pragma unroll 2
    for (int k = 0; k < IN; k++) {
        float f = my[k];
        u64 uk = pk2(f, f);
        const ulonglong2* w = (const ulonglong2*)(wcol + k * 128);
#pragma unroll
        for (int q = 0; q < 16; q++) {
            ulonglong2 ww = w[q];
            f2fma(acc[2 * q],     uk, ww.x);
            f2fma(acc[2 * q + 1], uk, ww.y);
        }
    }
}

// ============================================================
// Kernel 1: Z-branch.  Zj[j][b][:] = MLP_j(Z[b])
// ============================================================
__global__ void __launch_bounds__(128) z_kernel(const float* __restrict__ Zin,
                                                const float* __restrict__ Wz0,
                                                const float* __restrict__ Wz,
                                                const float* __restrict__ Wlz) {
    __shared__ __align__(16) float w0[20 * 64];
    __shared__ __align__(16) float w1[64 * 64];
    __shared__ __align__(16) float w2[64 * 64];
    __shared__ __align__(16) float wl[64 * 16];
    const int j   = blockIdx.x >> 6;
    const int tid = threadIdx.x;
    const int b   = ((blockIdx.x & 63) << 7) + tid;

    {
        const float4* p0 = (const float4*)(Wz0 + j * 1280);
        const float4* p1 = (const float4*)(Wz  + j * 8192);
        const float4* p2 = (const float4*)(Wz  + j * 8192 + 4096);
        const float4* pl = (const float4*)(Wlz + j * 1024);
        for (int t = tid; t < 320;  t += 128) ((float4*)w0)[t] = p0[t];
        for (int t = tid; t < 1024; t += 128) ((float4*)w1)[t] = p1[t];
        for (int t = tid; t < 1024; t += 128) ((float4*)w2)[t] = p2[t];
        for (int t = tid; t < 256;  t += 128) ((float4*)wl)[t] = pl[t];
    }
    __syncthreads();

    float zv[20];
    const float4* zr = (const float4*)(Zin + (size_t)b * DZF);
#pragma unroll
    for (int t = 0; t < 5; t++) {
        float4 v = zr[t];
        zv[4 * t] = v.x; zv[4 * t + 1] = v.y; zv[4 * t + 2] = v.z; zv[4 * t + 3] = v.w;
    }

    float h1[64], h2[64], o[16];
    dense_reg<20, 64, true >(zv, w0, h1);
    dense_reg<64, 64, true >(h1, w1, h2);
    dense_reg<64, 64, true >(h2, w2, h1);
    dense_reg<64, 16, false>(h1, wl, o);

    float4* dst = (float4*)(g_Zj + (size_t)(j * B_SZ + b) * 16);
#pragma unroll
    for (int t = 0; t < 4; t++)
        dst[t] = make_float4(o[4 * t], o[4 * t + 1], o[4 * t + 2], o[4 * t + 3]);
}

// ============================================================
// Kernel 2: D_j[b][:] = Zj_j[b]·Wu0[48:64] + Z[b]·Wu0[64:84]
// grid (32, 3) x 256 (one thread per b).
// ============================================================
__global__ void __launch_bounds__(256) d_kernel(const float* __restrict__ Zin,
                                                const float* __restrict__ Wu0) {
    __shared__ __align__(16) float w[36 * 128];
    const int j   = blockIdx.y;
    const int tid = threadIdx.x;
    const int b   = blockIdx.x * 256 + tid;

    const float4* src = (const float4*)(Wu0 + 48 * 128);
    for (int t = tid; t < 36 * 32; t += 256) ((float4*)w)[t] = src[t];
    __syncthreads();

    float in[36];
    const float4* zj = (const float4*)(g_Zj + (size_t)(j * B_SZ + b) * 16);
#pragma unroll
    for (int t = 0; t < 4; t++) {
        float4 v = zj[t];
        in[4 * t] = v.x; in[4 * t + 1] = v.y; in[4 * t + 2] = v.z; in[4 * t + 3] = v.w;
    }
    const float4* zr = (const float4*)(Zin + (size_t)b * DZF);
#pragma unroll
    for (int t = 0; t < 5; t++) {
        float4 v = zr[t];
        in[16 + 4 * t] = v.x; in[17 + 4 * t] = v.y; in[18 + 4 * t] = v.z; in[19 + 4 * t] = v.w;
    }

    float* dst = g_D + (size_t)(j * B_SZ + b) * 128;
    u64 acc[32];
#pragma unroll
    for (int half = 0; half < 2; half++) {
        dense_half_reg<36>(in, w + half * 64, acc);
        float4* d4 = (float4*)(dst + half * 64);
#pragma unroll
        for (int q = 0; q < 16; q++) {
            float a, bb, c, d;
            upk2(acc[2 * q], a, bb); upk2(acc[2 * q + 1], c, d);
            d4[q] = make_float4(a, bb, c, d);
        }
    }
}

// ============================================================
// Kernel 3: X-branch + E.  Xi = MLP_i(X[b,p]) (Wlx[DX-1] bug kept),
// then E_i = [X, Xi]·Wu0[0:48], stored column-major g_E[i][k][row].
// grid (1600, 3) x 256.
// ============================================================
__global__ void __launch_bounds__(256) x_kernel(const float* __restrict__ Xin,
                                                const float* __restrict__ Wx0,
                                                const float* __restrict__ Wx,
                                                const float* __restrict__ Wlx,
                                                const float* __restrict__ Wu0) {
    extern __shared__ float xs[];
    float* w0  = xs;                 // 32*64
    float* w1  = w0 + 2048;          // 64*64
    float* w2  = w1 + 4096;          // 64*64
    float* wl  = w2 + 4096;          // 64*16
    float* wu0 = wl + 1024;          // 48*128
    const int i   = blockIdx.y;
    const int tid = threadIdx.x;

    {
        const float4* p0 = (const float4*)(Wx0 + i * 2048);
        const float4* p1 = (const float4*)(Wx  + i * 8192);
        const float4* p2 = (const float4*)(Wx  + i * 8192 + 4096);
        const float4* pl = (const float4*)(Wlx + 2 * 1024);   // Wlx[DX-1] always (ref bug)
        const float4* pu = (const float4*)Wu0;                 // rows 0..47
        for (int t = tid; t < 512;  t += 256) ((float4*)w0)[t] = p0[t];
        for (int t = tid; t < 1024; t += 256) ((float4*)w1)[t] = p1[t];
        for (int t = tid; t < 1024; t += 256) ((float4*)w2)[t] = p2[t];
        for (int t = tid; t < 256;  t += 256) ((float4*)wl)[t] = pl[t];
        for (int t = tid; t < 1536; t += 256) ((float4*)wu0)[t] = pu[t];
    }
    __syncthreads();

    const int r = blockIdx.x * 256 + tid;  // row in [0, NROWS)
    float in48[48];
    const float4* xr = (const float4*)(Xin + (size_t)r * DXF);
#pragma unroll
    for (int t = 0; t < 8; t++) {
        float4 v = xr[t];
        in48[4 * t] = v.x; in48[4 * t + 1] = v.y; in48[4 * t + 2] = v.z; in48[4 * t + 3] = v.w;
    }

    {
        float xv[32];
#pragma unroll
        for (int t = 0; t < 32; t++) xv[t] = in48[t];
        float h1[64], h2[64], o[16];
        dense_reg<32, 64, true >(xv, w0, h1);
        dense_reg<64, 64, true >(h1, w1, h2);
        dense_reg<64, 64, true >(h2, w2, h1);
        dense_reg<64, 16, false>(h1, wl, o);
#pragma unroll
        for (int t = 0; t < 16; t++) in48[32 + t] = o[t];
    }

    // E = in48 · Wu0[0:48]  (no elu), column-major store: g_E[(i*128+k)*NROWS + r]
    float* ebase = g_E + (size_t)i * 128 * NROWS + r;
    u64 acc[32];
#pragma unroll
    for (int half = 0; half < 2; half++) {
        dense_half_reg<48>(in48, wu0 + half * 64, acc);
        float* eb = ebase + (size_t)(half * 64) * NROWS;
#pragma unroll
        for (int q = 0; q < 32; q++) {
            float lo, hi; upk2(acc[q], lo, hi);
            eb[(size_t)(2 * q) * NROWS]     = lo;
            eb[(size_t)(2 * q + 1) * NROWS] = hi;
        }
    }
}

// ============================================================
// Kernel 4: U layers 2-3 + score, per (pair, row).
// layer-1 activation = elu(E_i[row] + D_j[b]) built into per-thread slab.
// Two 64-output passes per layer (acc = 32 u64 -> no spills).
// ============================================================
__global__ void __launch_bounds__(256) u_kernel(const float* __restrict__ Wu,
                                                const float* __restrict__ Wlast,
                                                int blockOff) {
    extern __shared__ float smem[];
    float* slab = smem;                   // 256 * 129
    float* wbuf = smem + 256 * 129;       // 16384
    float* wl   = wbuf + 16384;           // 128

    const int tid  = threadIdx.x;
    const size_t r = (size_t)(blockIdx.x + blockOff) * 256 + tid;  // [0, 9*NROWS)
    const int pair = (int)(r / NROWS);
    const int rem  = (int)(r - (size_t)pair * NROWS);
    const int b    = rem / NPROD;
    const int i    = pair / 3;
    const int j    = pair - 3 * i;
    float* my = slab + tid * 129;

    // stage layer-2 weights + wlast
    for (int t = tid; t < 4096; t += 256) ((float4*)wbuf)[t] = ((const float4*)Wu)[t];
    if (tid < 32) ((float4*)wl)[tid] = ((const float4*)Wlast)[tid];

    // build u1 = elu(E + D) into slab
    {
        const float* Ep = g_E + (size_t)i * 128 * NROWS + rem;
        const float* Dp = g_D + (size_t)(j * B_SZ + b) * 128;
#pragma unroll 4
        for (int k = 0; k < 128; k++)
            my[k] = eluf(Ep[(size_t)k * NROWS] + Dp[k]);
    }
    __syncthreads();

    u64 accA[32], accB[32];

    // ---- layer 2: 128 -> 128 (Wu[0]) ----
    dense_half_slab<128>(my, wbuf,      accA);
    dense_half_slab<128>(my, wbuf + 64, accB);
#pragma unroll
    for (int q = 0; q < 32; q++) {
        float lo, hi;
        upk2(accA[q], lo, hi); my[2 * q] = eluf(lo);      my[2 * q + 1] = eluf(hi);
        upk2(accB[q], lo, hi); my[64 + 2 * q] = eluf(lo); my[64 + 2 * q + 1] = eluf(hi);
    }

    // ---- layer 3: 128 -> 128 (Wu[1]) + dot Wlast ----
    __syncthreads();
    for (int t = tid; t < 4096; t += 256) ((float4*)wbuf)[t] = ((const float4*)(Wu + 16384))[t];
    __syncthreads();
    dense_half_slab<128>(my, wbuf,      accA);
    dense_half_slab<128>(my, wbuf + 64, accB);

    float s = 0.f;
#pragma unroll
    for (int q = 0; q < 32; q++) {
        float lo, hi;
        upk2(accA[q], lo, hi);
        s += eluf(lo) * wl[2 * q] + eluf(hi) * wl[2 * q + 1];
        upk2(accB[q], lo, hi);
        s += eluf(lo) * wl[64 + 2 * q] + eluf(hi) * wl[64 + 2 * q + 1];
    }
    g_scores[r] = s;
}

// ============================================================
// Kernel 5: softmax over n per (pair, b), accumulate & average.
// ============================================================
__global__ void __launch_bounds__(64) smax_kernel(float* __restrict__ out) {
    __shared__ float red[64];
    const int b   = blockIdx.x;
    const int tid = threadIdx.x;
    const bool act = tid < NPROD;
    float accv = 0.f;

    for (int pair = 0; pair < 9; pair++) {
        float s = act ? g_scores[(size_t)(pair * B_SZ + b) * NPROD + tid] : -1e30f;
        red[tid] = s;
        __syncthreads();
#pragma unroll
        for (int st = 32; st > 0; st >>= 1) {
            if (tid < st) red[tid] = fmaxf(red[tid], red[tid + st]);
            __syncthreads();
        }
        float mx = red[0];
        __syncthreads();
        float e = act ? expf(s - mx) : 0.f;
        red[tid] = e;
        __syncthreads();
#pragma unroll
        for (int st = 32; st > 0; st >>= 1) {
            if (tid < st) red[tid] += red[tid + st];
            __syncthreads();
        }
        float sum = red[0];
        __syncthreads();
        accv += 1e-6f + e / sum;
    }
    if (act)
        out[(size_t)b * NPROD + tid] = accv * (1.f / (1.f + 1e-6f * (float)NPROD)) / 9.f;
}

// ============================================================
extern "C" void kernel_launch(void* const* d_in, const int* in_sizes, int n_in,
                              void* d_out, int out_size) {
    const float* X     = (const float*)d_in[0];
    const float* Z     = (const float*)d_in[1];
    const float* Wx0   = (const float*)d_in[2];
    const float* Wx    = (const float*)d_in[3];
    const float* Wlx   = (const float*)d_in[4];
    const float* Wz0   = (const float*)d_in[5];
    const float* Wz    = (const float*)d_in[6];
    const float* Wlz   = (const float*)d_in[7];
    const float* Wu0   = (const float*)d_in[8];
    const float* Wu    = (const float*)d_in[9];
    const float* Wlast = (const float*)d_in[10];
    float* out = (float*)d_out;

    const size_t smemX = (size_t)(2048 + 4096 + 4096 + 1024 + 6144) * sizeof(float); // 69632
    const size_t smemU = (size_t)(256 * 129 + 16384 + 128) * sizeof(float);          // 198144
    cudaFuncSetAttribute(x_kernel, cudaFuncAttributeMaxDynamicSharedMemorySize, (int)smemX);
    cudaFuncSetAttribute(u_kernel, cudaFuncAttributeMaxDynamicSharedMemorySize, (int)smemU);

    z_kernel<<<192, 128>>>(Z, Wz0, Wz, Wlz);
    d_kernel<<<dim3(32, 3), 256>>>(Z, Wu0);
    x_kernel<<<dim3(1600, 3), 256, smemX>>>(X, Wx0, Wx, Wlx, Wu0);
    u_kernel<<<7200, 256, smemU>>>(Wu, Wlast, 0);
    u_kernel<<<7200, 256, smemU>>>(Wu, Wlast, 7200);
    smax_kernel<<<8192, 64>>>(out);
}

// round 6
// speedup vs baseline: 1.8234x; 1.7379x over previous
#include <cuda_runtime.h>

typedef unsigned long long u64;

#define B_SZ   8192
#define NPROD  50
#define DXF    32
#define DZF    20
#define NROWS  (B_SZ * NPROD)       // 409600

// ---------------- scratch (device globals, no allocation) ----------------
__device__ float g_Zj[3 * B_SZ * 16];                    // [KZ][B][16]
__device__ float g_D[3 * B_SZ * 128];                    // [KZ][B][128]
__device__ float g_E[(size_t)3 * 128 * NROWS];           // [KX][128][NROWS] column-major
__device__ float g_scores[9 * NROWS];                    // [pair][B][n]

// ---------------- packed f32x2 helpers ----------------
__device__ __forceinline__ u64 pk2(float lo, float hi) {
    u64 r; asm("mov.b64 %0, {%1, %2};" : "=l"(r) : "f"(lo), "f"(hi)); return r;
}
__device__ __forceinline__ void upk2(u64 v, float& lo, float& hi) {
    asm("mov.b64 {%0, %1}, %2;" : "=f"(lo), "=f"(hi) : "l"(v));
}
__device__ __forceinline__ void f2fma(u64& d, u64 a, u64 b) {
    asm("fma.rn.f32x2 %0, %1, %2, %0;" : "+l"(d) : "l"(a), "l"(b));
}
__device__ __forceinline__ float eluf(float x) { return x > 0.f ? x : expm1f(x); }

// Dense layer, register input/output, weights in shared. [IN][OUT] row-major.
template<int IN, int OUT, bool ELU>
__device__ __forceinline__ void dense_reg(const float (&in)[IN], const float* wsh, float (&out)[OUT]) {
    u64 acc[OUT / 2];
#pragma unroll
    for (int jj = 0; jj < OUT / 2; jj++) acc[jj] = 0ull;
#pragma unroll
    for (int k = 0; k < IN; k++) {
        u64 xk = pk2(in[k], in[k]);
        const ulonglong2* w = (const ulonglong2*)(wsh + k * OUT);
#pragma unroll
        for (int q = 0; q < OUT / 4; q++) {
            ulonglong2 ww = w[q];
            f2fma(acc[2 * q],     xk, ww.x);
            f2fma(acc[2 * q + 1], xk, ww.y);
        }
    }
#pragma unroll
    for (int jj = 0; jj < OUT / 2; jj++) {
        float lo, hi; upk2(acc[jj], lo, hi);
        out[2 * jj]     = ELU ? eluf(lo) : lo;
        out[2 * jj + 1] = ELU ? eluf(hi) : hi;
    }
}

// Half-width (64-out) accumulation pass, register input, weight row stride 128.
template<int IN>
__device__ __forceinline__ void dense_half_reg(const float (&in)[IN], const float* wcol, u64 (&acc)[32]) {
#pragma unroll
    for (int q = 0; q < 32; q++) acc[q] = 0ull;
#pragma unroll
    for (int k = 0; k < IN; k++) {
        u64 uk = pk2(in[k], in[k]);
        const ulonglong2* w = (const ulonglong2*)(wcol + k * 128);
#pragma unroll
        for (int q = 0; q < 16; q++) {
            ulonglong2 ww = w[q];
            f2fma(acc[2 * q],     uk, ww.x);
            f2fma(acc[2 * q + 1], uk, ww.y);
        }
    }
}

// ============================================================
// Kernel 1: Z-branch.  Zj[j][b][:] = MLP_j(Z[b])
// ============================================================
__global__ void __launch_bounds__(128) z_kernel(const float* __restrict__ Zin,
                                                const float* __restrict__ Wz0,
                                                const float* __restrict__ Wz,
                                                const float* __restrict__ Wlz) {
    __shared__ __align__(16) float w0[20 * 64];
    __shared__ __align__(16) float w1[64 * 64];
    __shared__ __align__(16) float w2[64 * 64];
    __shared__ __align__(16) float wl[64 * 16];
    const int j   = blockIdx.x >> 6;
    const int tid = threadIdx.x;
    const int b   = ((blockIdx.x & 63) << 7) + tid;

    {
        const float4* p0 = (const float4*)(Wz0 + j * 1280);
        const float4* p1 = (const float4*)(Wz  + j * 8192);
        const float4* p2 = (const float4*)(Wz  + j * 8192 + 4096);
        const float4* pl = (const float4*)(Wlz + j * 1024);
        for (int t = tid; t < 320;  t += 128) ((float4*)w0)[t] = p0[t];
        for (int t = tid; t < 1024; t += 128) ((float4*)w1)[t] = p1[t];
        for (int t = tid; t < 1024; t += 128) ((float4*)w2)[t] = p2[t];
        for (int t = tid; t < 256;  t += 128) ((float4*)wl)[t] = pl[t];
    }
    __syncthreads();

    float zv[20];
    const float4* zr = (const float4*)(Zin + (size_t)b * DZF);
#pragma unroll
    for (int t = 0; t < 5; t++) {
        float4 v = zr[t];
        zv[4 * t] = v.x; zv[4 * t + 1] = v.y; zv[4 * t + 2] = v.z; zv[4 * t + 3] = v.w;
    }

    float h1[64], h2[64], o[16];
    dense_reg<20, 64, true >(zv, w0, h1);
    dense_reg<64, 64, true >(h1, w1, h2);
    dense_reg<64, 64, true >(h2, w2, h1);
    dense_reg<64, 16, false>(h1, wl, o);

    float4* dst = (float4*)(g_Zj + (size_t)(j * B_SZ + b) * 16);
#pragma unroll
    for (int t = 0; t < 4; t++)
        dst[t] = make_float4(o[4 * t], o[4 * t + 1], o[4 * t + 2], o[4 * t + 3]);
}

// ============================================================
// Kernel 2: D_j[b][:] = Zj_j[b]·Wu0[48:64] + Z[b]·Wu0[64:84]
// ============================================================
__global__ void __launch_bounds__(256) d_kernel(const float* __restrict__ Zin,
                                                const float* __restrict__ Wu0) {
    __shared__ __align__(16) float w[36 * 128];
    const int j   = blockIdx.y;
    const int tid = threadIdx.x;
    const int b   = blockIdx.x * 256 + tid;

    const float4* src = (const float4*)(Wu0 + 48 * 128);
    for (int t = tid; t < 36 * 32; t += 256) ((float4*)w)[t] = src[t];
    __syncthreads();

    float in[36];
    const float4* zj = (const float4*)(g_Zj + (size_t)(j * B_SZ + b) * 16);
#pragma unroll
    for (int t = 0; t < 4; t++) {
        float4 v = zj[t];
        in[4 * t] = v.x; in[4 * t + 1] = v.y; in[4 * t + 2] = v.z; in[4 * t + 3] = v.w;
    }
    const float4* zr = (const float4*)(Zin + (size_t)b * DZF);
#pragma unroll
    for (int t = 0; t < 5; t++) {
        float4 v = zr[t];
        in[16 + 4 * t] = v.x; in[17 + 4 * t] = v.y; in[18 + 4 * t] = v.z; in[19 + 4 * t] = v.w;
    }

    float* dst = g_D + (size_t)(j * B_SZ + b) * 128;
    u64 acc[32];
#pragma unroll
    for (int half = 0; half < 2; half++) {
        dense_half_reg<36>(in, w + half * 64, acc);
        float4* d4 = (float4*)(dst + half * 64);
#pragma unroll
        for (int q = 0; q < 16; q++) {
            float a, bb, c, d;
            upk2(acc[2 * q], a, bb); upk2(acc[2 * q + 1], c, d);
            d4[q] = make_float4(a, bb, c, d);
        }
    }
}

// ============================================================
// Kernel 3: X-branch + E.  Xi = MLP_i(X[b,p]) (Wlx[DX-1] bug kept),
// then E_i = [X, Xi]·Wu0[0:48], stored column-major g_E[i][k][row].
// ============================================================
__global__ void __launch_bounds__(256) x_kernel(const float* __restrict__ Xin,
                                                const float* __restrict__ Wx0,
                                                const float* __restrict__ Wx,
                                                const float* __restrict__ Wlx,
                                                const float* __restrict__ Wu0) {
    extern __shared__ float xs[];
    float* w0  = xs;                 // 32*64
    float* w1  = w0 + 2048;          // 64*64
    float* w2  = w1 + 4096;          // 64*64
    float* wl  = w2 + 4096;          // 64*16
    float* wu0 = wl + 1024;          // 48*128
    const int i   = blockIdx.y;
    const int tid = threadIdx.x;

    {
        const float4* p0 = (const float4*)(Wx0 + i * 2048);
        const float4* p1 = (const float4*)(Wx  + i * 8192);
        const float4* p2 = (const float4*)(Wx  + i * 8192 + 4096);
        const float4* pl = (const float4*)(Wlx + 2 * 1024);   // Wlx[DX-1] always (ref bug)
        const float4* pu = (const float4*)Wu0;                 // rows 0..47
        for (int t = tid; t < 512;  t += 256) ((float4*)w0)[t] = p0[t];
        for (int t = tid; t < 1024; t += 256) ((float4*)w1)[t] = p1[t];
        for (int t = tid; t < 1024; t += 256) ((float4*)w2)[t] = p2[t];
        for (int t = tid; t < 256;  t += 256) ((float4*)wl)[t] = pl[t];
        for (int t = tid; t < 1536; t += 256) ((float4*)wu0)[t] = pu[t];
    }
    __syncthreads();

    const int r = blockIdx.x * 256 + tid;  // row in [0, NROWS)
    float in48[48];
    const float4* xr = (const float4*)(Xin + (size_t)r * DXF);
#pragma unroll
    for (int t = 0; t < 8; t++) {
        float4 v = xr[t];
        in48[4 * t] = v.x; in48[4 * t + 1] = v.y; in48[4 * t + 2] = v.z; in48[4 * t + 3] = v.w;
    }

    {
        float xv[32];
#pragma unroll
        for (int t = 0; t < 32; t++) xv[t] = in48[t];
        float h1[64], h2[64], o[16];
        dense_reg<32, 64, true >(xv, w0, h1);
        dense_reg<64, 64, true >(h1, w1, h2);
        dense_reg<64, 64, true >(h2, w2, h1);
        dense_reg<64, 16, false>(h1, wl, o);
#pragma unroll
        for (int t = 0; t < 16; t++) in48[32 + t] = o[t];
    }

    float* ebase = g_E + (size_t)i * 128 * NROWS + r;
    u64 acc[32];
#pragma unroll
    for (int half = 0; half < 2; half++) {
        dense_half_reg<48>(in48, wu0 + half * 64, acc);
        float* eb = ebase + (size_t)(half * 64) * NROWS;
#pragma unroll
        for (int q = 0; q < 32; q++) {
            float lo, hi; upk2(acc[q], lo, hi);
            eb[(size_t)(2 * q) * NROWS]     = lo;
            eb[(size_t)(2 * q + 1) * NROWS] = hi;
        }
    }
}

// ============================================================
// Kernel 4: tiled GEMM U-kernel.
// Block = 512 threads, tile 256 rows x 128 cols, micro 4x16.
// A tile K-major in shared (pitch 260); W double-buffered 32-k chunks.
// ============================================================
#define APITCH 260
#define A_FLOATS (128 * APITCH)          // 33280
#define WB_OFF   A_FLOATS                // 2 * 4096 floats
#define DSH_OFF  (WB_OFF + 8192)         // 8 * 132 floats
#define WL_OFF   (DSH_OFF + 1056)        // 128 floats
#define U_SMEM_FLOATS (WL_OFF + 128)     // 42656 floats = 170624 B

__global__ void __launch_bounds__(512) u_kernel(const float* __restrict__ Wu,
                                                const float* __restrict__ Wlast) {
    extern __shared__ float sm[];
    float* Asm = sm;
    float* Wb  = sm + WB_OFF;
    float* Dsh = sm + DSH_OFF;
    float* wl  = sm + WL_OFF;

    const int tid  = threadIdx.x;
    const int bx   = blockIdx.x;            // 0..14399
    const int pair = bx / 1600;
    const int tile = bx - pair * 1600;
    const int r0   = tile * 256;
    const int i    = pair / 3;
    const int j    = pair - 3 * i;
    const int b0   = r0 / NPROD;

    const int wid    = tid >> 5;
    const int warp_c = wid & 1;
    const int warp_r = wid >> 1;
    const int lane   = tid & 31;
    const int lr     = lane & 7;
    const int lc     = lane >> 3;
    const int row_off = warp_r * 32 + lr * 4;      // 0..252
    const int col_off = warp_c * 64 + lc * 16;     // 0..112

    // ---- stage D rows + wlast ----
    for (int t = tid; t < 1024; t += 512) {
        int bl = t >> 7, k = t & 127;
        int bb = b0 + bl;
        if (bb < B_SZ) Dsh[bl * 132 + k] = g_D[((size_t)j * B_SZ + bb) * 128 + k];
    }
    if (tid < 128) wl[tid] = Wlast[tid];
    __syncthreads();

    // ---- prologue: A[k][m] = elu(E[i][k][r0+m] + D[j][b(m)][k]) ----
    {
        const float* Eb = g_E + (size_t)i * 128 * NROWS + r0;
#pragma unroll 4
        for (int it = 0; it < 16; it++) {
            int v = tid + it * 512;           // float4 index
            int k = v >> 6;
            int m = (v & 63) * 4;
            float4 e = *(const float4*)(Eb + (size_t)k * NROWS + m);
            int rg = r0 + m;
            float o0 = eluf(e.x + Dsh[((rg    ) / NPROD - b0) * 132 + k]);
            float o1 = eluf(e.y + Dsh[((rg + 1) / NPROD - b0) * 132 + k]);
            float o2 = eluf(e.z + Dsh[((rg + 2) / NPROD - b0) * 132 + k]);
            float o3 = eluf(e.w + Dsh[((rg + 3) / NPROD - b0) * 132 + k]);
            *(float4*)(Asm + k * APITCH + m) = make_float4(o0, o1, o2, o3);
        }
    }
    __syncthreads();

    u64 acc[32];

#pragma unroll 1
    for (int layer = 0; layer < 2; layer++) {
        const float4* Wg4 = (const float4*)(Wu + layer * 16384);

        // stage chunk 0 into buffer 0
        ((float4*)Wb)[tid]       = Wg4[tid];
        ((float4*)Wb)[tid + 512] = Wg4[tid + 512];
        __syncthreads();

#pragma unroll
        for (int q = 0; q < 32; q++) acc[q] = 0ull;

        float4 wr0, wr1;
#pragma unroll 1
        for (int kc = 0; kc < 4; kc++) {
            if (kc < 3) {
                wr0 = Wg4[(kc + 1) * 1024 + tid];
                wr1 = Wg4[(kc + 1) * 1024 + 512 + tid];
            }
            const float* Bc = Wb + (kc & 1) * 4096 + col_off;
            const float* Ac = Asm + kc * 32 * APITCH + row_off;
#pragma unroll 4
            for (int kk = 0; kk < 32; kk++) {
                float4 av = *(const float4*)(Ac + kk * APITCH);
                const ulonglong2* bp = (const ulonglong2*)(Bc + kk * 128);
                ulonglong2 q0 = bp[0], q1 = bp[1], q2 = bp[2], q3 = bp[3];
                u64 bv[8] = {q0.x, q0.y, q1.x, q1.y, q2.x, q2.y, q3.x, q3.y};
                u64 av2[4];
                av2[0] = pk2(av.x, av.x); av2[1] = pk2(av.y, av.y);
                av2[2] = pk2(av.z, av.z); av2[3] = pk2(av.w, av.w);
#pragma unroll
                for (int r = 0; r < 4; r++)
#pragma unroll
                    for (int c2 = 0; c2 < 8; c2++)
                        f2fma(acc[r * 8 + c2], av2[r], bv[c2]);
            }
            if (kc < 3) {
                __syncthreads();
                float4* dst = (float4*)(Wb + ((kc + 1) & 1) * 4096);
                dst[tid]       = wr0;
                dst[tid + 512] = wr1;
                __syncthreads();
            }
        }
        __syncthreads();   // all warps done reading A/Wb for this layer

        if (layer == 0) {
            // transition: A[c][m] = elu(out[m][c])
#pragma unroll
            for (int c2 = 0; c2 < 8; c2++) {
                float lo0, hi0, lo1, hi1, lo2, hi2, lo3, hi3;
                upk2(acc[0 * 8 + c2], lo0, hi0);
                upk2(acc[1 * 8 + c2], lo1, hi1);
                upk2(acc[2 * 8 + c2], lo2, hi2);
                upk2(acc[3 * 8 + c2], lo3, hi3);
                int cA = col_off + 2 * c2;
                *(float4*)(Asm + cA * APITCH + row_off) =
                    make_float4(eluf(lo0), eluf(lo1), eluf(lo2), eluf(lo3));
                *(float4*)(Asm + (cA + 1) * APITCH + row_off) =
                    make_float4(eluf(hi0), eluf(hi1), eluf(hi2), eluf(hi3));
            }
            __syncthreads();
        }
    }

    // ---- epilogue: score = sum_c elu(out3[m][c]) * wlast[c] ----
    float s0 = 0.f, s1 = 0.f, s2 = 0.f, s3 = 0.f;
#pragma unroll
    for (int c2 = 0; c2 < 8; c2++) {
        float wlo = wl[col_off + 2 * c2];
        float whi = wl[col_off + 2 * c2 + 1];
        float lo, hi;
        upk2(acc[0 * 8 + c2], lo, hi); s0 += eluf(lo) * wlo + eluf(hi) * whi;
        upk2(acc[1 * 8 + c2], lo, hi); s1 += eluf(lo) * wlo + eluf(hi) * whi;
        upk2(acc[2 * 8 + c2], lo, hi); s2 += eluf(lo) * wlo + eluf(hi) * whi;
        upk2(acc[3 * 8 + c2], lo, hi); s3 += eluf(lo) * wlo + eluf(hi) * whi;
    }
    // reduce across the 8 column-chunks (overlay Wb; synced above)
    float* sred = Wb;
    const int q8 = warp_c * 4 + lc;
    sred[q8 * 260 + row_off + 0] = s0;
    sred[q8 * 260 + row_off + 1] = s1;
    sred[q8 * 260 + row_off + 2] = s2;
    sred[q8 * 260 + row_off + 3] = s3;
    __syncthreads();
    if (tid < 256) {
        float s = 0.f;
#pragma unroll
        for (int q = 0; q < 8; q++) s += sred[q * 260 + tid];
        g_scores[(size_t)pair * NROWS + r0 + tid] = s;
    }
}

// ============================================================
// Kernel 5: softmax over n per (pair, b), accumulate & average.
// ============================================================
__global__ void __launch_bounds__(64) smax_kernel(float* __restrict__ out) {
    __shared__ float red[64];
    const int b   = blockIdx.x;
    const int tid = threadIdx.x;
    const bool act = tid < NPROD;
    float accv = 0.f;

    for (int pair = 0; pair < 9; pair++) {
        float s = act ? g_scores[(size_t)(pair * B_SZ + b) * NPROD + tid] : -1e30f;
        red[tid] = s;
        __syncthreads();
#pragma unroll
        for (int st = 32; st > 0; st >>= 1) {
            if (tid < st) red[tid] = fmaxf(red[tid], red[tid + st]);
            __syncthreads();
        }
        float mx = red[0];
        __syncthreads();
        float e = act ? expf(s - mx) : 0.f;
        red[tid] = e;
        __syncthreads();
#pragma unroll
        for (int st = 32; st > 0; st >>= 1) {
            if (tid < st) red[tid] += red[tid + st];
            __syncthreads();
        }
        float sum = red[0];
        __syncthreads();
        accv += 1e-6f + e / sum;
    }
    if (act)
        out[(size_t)b * NPROD + tid] = accv * (1.f / (1.f + 1e-6f * (float)NPROD)) / 9.f;
}

// ============================================================
extern "C" void kernel_launch(void* const* d_in, const int* in_sizes, int n_in,
                              void* d_out, int out_size) {
    const float* X     = (const float*)d_in[0];
    const float* Z     = (const float*)d_in[1];
    const float* Wx0   = (const float*)d_in[2];
    const float* Wx    = (const float*)d_in[3];
    const float* Wlx   = (const float*)d_in[4];
    const float* Wz0   = (const float*)d_in[5];
    const float* Wz    = (const float*)d_in[6];
    const float* Wlz   = (const float*)d_in[7];
    const float* Wu0   = (const float*)d_in[8];
    const float* Wu    = (const float*)d_in[9];
    const float* Wlast = (const float*)d_in[10];
    float* out = (float*)d_out;

    const size_t smemX = (size_t)(2048 + 4096 + 4096 + 1024 + 6144) * sizeof(float); // 69632
    const size_t smemU = (size_t)U_SMEM_FLOATS * sizeof(float);                      // 170624
    cudaFuncSetAttribute(x_kernel, cudaFuncAttributeMaxDynamicSharedMemorySize, (int)smemX);
    cudaFuncSetAttribute(u_kernel, cudaFuncAttributeMaxDynamicSharedMemorySize, (int)smemU);

    z_kernel<<<192, 128>>>(Z, Wz0, Wz, Wlz);
    d_kernel<<<dim3(32, 3), 256>>>(Z, Wu0);
    x_kernel<<<dim3(1600, 3), 256, smemX>>>(X, Wx0, Wx, Wlx, Wu0);
    u_kernel<<<14400, 512, smemU>>>(Wu, Wlast);
    smax_kernel<<<8192, 64>>>(out);
}